// round 8
// baseline (speedup 1.0000x reference)
#include <cuda_runtime.h>
#include <cuda_bf16.h>

// Problem constants
#define NXS    41
#define GTOT   68921          // 41^3
#define NX2    1681           // 41^2
#define WPAD   2156           // padded word count (multiple of 4)
#define CHUNKS 539            // chunk = 128 voxels (4 mask words)
#define FULLCH 538
#define KPK    4
#define NEGV   (-1.0e9f)
#define VTH    (-1.0e8f)
#define NPAIR  512            // B*N*C = 1*128*4
#define FULLM  0xffffffffu

// Shifted sphere masks: S_a bit p <-> voxel g = p + a. Tail words zero.
__device__ unsigned int g_S[4][WPAD];
__device__ int g_list[4][CHUNKS];   // non-empty chunk ids per variant
__device__ int g_nlist[4];

// ---------------------------------------------------------------------------
// Kernel 1: shifted sphere masks from index arithmetic (bit-exact vs numpy)
// ---------------------------------------------------------------------------
__global__ __launch_bounds__(256) void init_masks_kernel()
{
    int a = blockIdx.y;
    int p = blockIdx.x * 256 + threadIdx.x;   // shifted bit position
    int g = p + a;                            // absolute voxel index
    bool ok = false;
    if (g < GTOT) {
        int i = g / NX2;
        int j = (g / NXS) % NXS;
        int k = g % NXS;
        float x = (float)((double)(i - 20) * 0.3);
        float y = (float)((double)(j - 20) * 0.3);
        float z = (float)((double)(k - 20) * 0.3);
        float s = __fadd_rn(__fadd_rn(__fmul_rn(x, x), __fmul_rn(y, y)), __fmul_rn(z, z));
        ok = (__fsqrt_rn(s) <= 6.0f);
    }
    unsigned int ballot = __ballot_sync(FULLM, ok);
    if ((threadIdx.x & 31) == 0) {
        int w = p >> 5;
        if (w < WPAD) g_S[a][w] = ballot;
    }
}

// ---------------------------------------------------------------------------
// Kernel 2: per-variant compact list of non-empty chunks (1 CTA, 4 warps)
// ---------------------------------------------------------------------------
__global__ __launch_bounds__(128) void build_lists_kernel()
{
    int a = threadIdx.x >> 5;
    int lane = threadIdx.x & 31;
    const unsigned int* S = g_S[a];
    int count = 0;
    for (int base = 0; base < CHUNKS; base += 32) {
        int c = base + lane;
        bool ne = false;
        if (c < CHUNKS)
            ne = (S[c * 4] | S[c * 4 + 1] | S[c * 4 + 2] | S[c * 4 + 3]) != 0u;
        unsigned int bal = __ballot_sync(FULLM, ne);
        int pos = count + __popc(bal & ((1u << lane) - 1u));
        if (ne) g_list[a][pos] = c;
        count += __popc(bal);
    }
    if (lane == 0) g_nlist[a] = count;
}

// order-preserving float->uint key; 0 = "masked" (below all real keys)
__device__ __forceinline__ unsigned int f2key(float v)
{
    int i = __float_as_int(v);
    return (unsigned int)(i ^ ((i >> 31) | 0x80000000));
}
__device__ __forceinline__ float key2f(unsigned int k)
{
    int i = (k & 0x80000000u) ? (int)(k ^ 0x80000000u) : (int)~k;
    return __int_as_float(i);
}
__device__ __forceinline__ unsigned int sext_bit(unsigned int w, int bitpos)
{
    return (unsigned int)(((int)(w << (31 - bitpos))) >> 31);
}

// ---------------------------------------------------------------------------
// Kernel 3 (fused): unmasked float4 chunk scan + verified argmax + NMS
// ---------------------------------------------------------------------------
__global__ __launch_bounds__(256) void peaks_kernel(
    const float* __restrict__ density,   // [512, G]
    const float* __restrict__ grid_xyz,  // [G, 3]
    const float* __restrict__ Rmats,     // [128, 3, 3]
    const float* __restrict__ tpos,      // [128, 3]
    const float* __restrict__ node_mask, // [128]
    float* __restrict__ out)             // 16384 floats
{
    __shared__ unsigned int smask[WPAD];    // live shifted bits
    __shared__ unsigned int ckey[CHUNKS];   // per-chunk max key (>= masked truth)
    __shared__ unsigned int swk[8];
    __shared__ int          sww[8];
    __shared__ float pk_score[KPK];
    __shared__ int   pk_idx[KPK];
    __shared__ int   pk_valid[KPK];
    __shared__ int   cur_i, cur_j, cur_k, cur_valid, s_done;
    __shared__ int   wlist[128];
    __shared__ int   wcount;

    const int pair = blockIdx.x;            // n*4 + c
    const int tid  = threadIdx.x;
    const int lane = tid & 31;
    const int wid  = tid >> 5;
    const int aoff = (-pair) & 3;           // alignment shift (voxels)
    const float4* __restrict__ dens4 =
        (const float4*)(density + (size_t)pair * GTOT + aoff);
    const unsigned int* __restrict__ S = g_S[aoff];
    const int* __restrict__ list = g_list[aoff];

    for (int w = tid; w < WPAD; w += 256) smask[w] = S[w];
    for (int c = tid; c < CHUNKS; c += 256) ckey[c] = 0u;
    __syncthreads();

    // ---- pass 1: UNMASKED per-chunk max over the non-empty chunk list ----
    const int nl = g_nlist[aoff];
    for (int e0 = wid * 4; e0 < nl; e0 += 32) {
        int    cc[4];
        float4 ff[4];
        #pragma unroll
        for (int b = 0; b < 4; ++b) {
            int e = min(e0 + b, nl - 1);           // dup-clamped tail
            cc[b] = __ldg(&list[e]);
            ff[b] = __ldg(dens4 + cc[b] * 32 + lane);
        }
        #pragma unroll
        for (int b = 0; b < 4; ++b) {
            float m = fmaxf(fmaxf(ff[b].x, ff[b].y), fmaxf(ff[b].z, ff[b].w));
            unsigned int r = __reduce_max_sync(FULLM, f2key(m));
            if (lane == 0 && e0 + b < nl) ckey[cc[b]] = r;
        }
    }
    __syncthreads();

    for (int t = 0; t < KPK; ++t) {
        // ---- verified argmax loop ----
        for (;;) {
            unsigned int bk = 0;
            int bc = 0x7FFFFFFF;
            for (int c = tid; c < CHUNKS; c += 256) {
                unsigned int k = ckey[c];
                if (k > bk) { bk = k; bc = c; }   // ascending: lowest c on ties
            }
            unsigned int wm = __reduce_max_sync(FULLM, bk);
            int cand = (bk == wm) ? bc : 0x7FFFFFFF;
            int wmin = (int)__reduce_min_sync(FULLM, (unsigned int)cand);
            if (lane == 0) { swk[wid] = wm; sww[wid] = wmin; }
            __syncthreads();
            if (wid == 0) {
                unsigned int k8 = (lane < 8) ? swk[lane] : 0u;
                int w8 = (lane < 8) ? sww[lane] : 0x7FFFFFFF;
                unsigned int fm = __reduce_max_sync(FULLM, k8);
                int c8 = (k8 == fm) ? w8 : 0x7FFFFFFF;
                int fc = (int)__reduce_min_sync(FULLM, (unsigned int)c8);
                // masked verification of chunk fc
                float4 f = __ldg(dens4 + fc * 32 + lane);
                unsigned int mw = smask[fc * 4 + (lane >> 3)];
                int sh = (lane & 7) * 4;
                unsigned int k0 = f2key(f.x) & sext_bit(mw, sh + 0);
                unsigned int k1 = f2key(f.y) & sext_bit(mw, sh + 1);
                unsigned int k2 = f2key(f.z) & sext_bit(mw, sh + 2);
                unsigned int k3 = f2key(f.w) & sext_bit(mw, sh + 3);
                unsigned int bestk = k0; int besti = 0;
                if (k1 > bestk) { bestk = k1; besti = 1; }
                if (k2 > bestk) { bestk = k2; besti = 2; }
                if (k3 > bestk) { bestk = k3; besti = 3; }
                unsigned int mk = __reduce_max_sync(FULLM, bestk);
                if (mk == fm) {
                    // accept: lowest-g argmax within chunk
                    int gl = fc * 128 + lane * 4 + besti;
                    int cg = (bestk == mk) ? gl : 0x7FFFFFFF;
                    int gp = (int)__reduce_min_sync(FULLM, (unsigned int)cg);
                    if (lane == 0) {
                        int gi = gp + aoff;          // absolute voxel index
                        float sc = key2f(fm);
                        int valid = (sc > VTH) ? 1 : 0;
                        pk_score[t] = sc;
                        pk_idx[t]   = gi;
                        pk_valid[t] = valid;
                        cur_valid = valid;
                        cur_i = gi / NX2;
                        cur_j = (gi / NXS) % NXS;
                        cur_k = gi % NXS;
                        wcount = 0;
                        s_done = 1;
                    }
                } else {
                    if (lane == 0) { ckey[fc] = mk; s_done = 0; }
                }
            }
            __syncthreads();
            if (s_done) break;
        }

        if (t < KPK - 1 && cur_valid) {
            // ---- clear bits in <=7x7x7 Chebyshev cube (shifted coords) ----
            int i0 = max(cur_i - 3, 0), i1 = min(cur_i + 3, NXS - 1);
            int j0 = max(cur_j - 3, 0), j1 = min(cur_j + 3, NXS - 1);
            int k0c = max(cur_k - 3, 0), k1c = min(cur_k + 3, NXS - 1);
            int nj = j1 - j0 + 1;
            int nrows = (i1 - i0 + 1) * nj;
            // rows >=35 bits apart -> never share a 32-bit word -> no races
            if (tid < nrows) {
                int i = i0 + tid / nj;
                int j = j0 + tid % nj;
                int pb = i * NX2 + j * NXS + k0c - aoff;   // shifted position
                int pe = pb + (k1c - k0c);
                int w0 = pb >> 5, w1 = pe >> 5;
                unsigned int b0 = (unsigned int)(pb & 31);
                unsigned int b1 = (unsigned int)(pe & 31);
                unsigned int hi = (b1 == 31u) ? FULLM : ((1u << (b1 + 1)) - 1u);
                int slot;
                if (w0 == w1) {
                    unsigned int msk = hi & ~((1u << b0) - 1u);
                    smask[w0] &= ~msk;
                    slot = atomicAdd(&wcount, 1);
                    wlist[slot] = w0 >> 2;
                } else {
                    smask[w0] &= ((1u << b0) - 1u);
                    smask[w1] &= ~hi;
                    slot = atomicAdd(&wcount, 2);
                    wlist[slot]     = w0 >> 2;
                    wlist[slot + 1] = w1 >> 2;
                }
            }
            __syncthreads();
            // ---- masked recompute of touched chunks (now exact) ----
            {
                int nw = wcount;   // <= 98, dups benign
                for (int e0 = wid * 4; e0 < nw; e0 += 32) {
                    int          cc[4];
                    float4       ff[4];
                    unsigned int mw_[4];
                    #pragma unroll
                    for (int b = 0; b < 4; ++b) {
                        int e = min(e0 + b, nw - 1);
                        int c = wlist[e];
                        cc[b] = (e0 + b < nw) ? c : -1;
                        ff[b] = __ldg(dens4 + c * 32 + lane);
                        mw_[b] = smask[c * 4 + (lane >> 3)];
                    }
                    int sh = (lane & 7) * 4;
                    #pragma unroll
                    for (int b = 0; b < 4; ++b) {
                        unsigned int mw = mw_[b];
                        unsigned int best = 0;
                        best = max(best, f2key(ff[b].x) & sext_bit(mw, sh + 0));
                        best = max(best, f2key(ff[b].y) & sext_bit(mw, sh + 1));
                        best = max(best, f2key(ff[b].z) & sext_bit(mw, sh + 2));
                        best = max(best, f2key(ff[b].w) & sext_bit(mw, sh + 3));
                        unsigned int r = __reduce_max_sync(FULLM, best);
                        if (lane == 0 && cc[b] >= 0) ckey[cc[b]] = r;
                    }
                }
            }
        }
        __syncthreads();
    }

    // ---- outputs ----
    // layout: coords_local[6144] | coords_global[6144] | scores[2048] | mask[2048]
    if (tid < KPK) {
        int k = tid;
        int n = pair >> 2;
        float nm = node_mask[n];
        int valid = pk_valid[k];
        float sc = valid ? pk_score[k] : NEGV;
        float x = 0.0f, y = 0.0f, z = 0.0f;
        if (valid) {
            int gi = pk_idx[k];
            x = grid_xyz[3 * gi + 0];
            y = grid_xyz[3 * gi + 1];
            z = grid_xyz[3 * gi + 2];
        }
        int o = (pair * KPK + k) * 3;
        out[o + 0] = x * nm;
        out[o + 1] = y * nm;
        out[o + 2] = z * nm;
        const float* R  = Rmats + n * 9;
        const float* tp = tpos + n * 3;
        float gx = R[0] * x + R[1] * y + R[2] * z + tp[0];
        float gy = R[3] * x + R[4] * y + R[5] * z + tp[1];
        float gz = R[6] * x + R[7] * y + R[8] * z + tp[2];
        out[6144 + o + 0] = gx * nm;
        out[6144 + o + 1] = gy * nm;
        out[6144 + o + 2] = gz * nm;
        out[12288 + pair * KPK + k] = sc * nm;
        out[14336 + pair * KPK + k] = (valid && nm != 0.0f) ? 1.0f : 0.0f;
    }
}

extern "C" void kernel_launch(void* const* d_in, const int* in_sizes, int n_in,
                              void* d_out, int out_size)
{
    // metadata order: density, grid_xyz, sphere_mask, coords_int, Rmats, tpos, node_mask
    const float* density   = (const float*)d_in[0];
    const float* grid_xyz  = (const float*)d_in[1];
    const float* Rmats     = (const float*)d_in[4];
    const float* tpos      = (const float*)d_in[5];
    const float* node_mask = (const float*)d_in[6];
    float* out = (float*)d_out;

    dim3 g1(270, 4);
    init_masks_kernel<<<g1, 256>>>();
    build_lists_kernel<<<1, 128>>>();
    peaks_kernel<<<NPAIR, 256>>>(density, grid_xyz, Rmats, tpos, node_mask, out);
}

// round 9
// speedup vs baseline: 1.0405x; 1.0405x over previous
#include <cuda_runtime.h>
#include <cuda_bf16.h>

// Problem constants
#define NXS    41
#define GTOT   68921          // 41^3
#define NX2    1681           // 41^2
#define WPAD   2156           // padded word count (multiple of 4)
#define CHUNKS 539            // chunk = 128 voxels (4 mask words)
#define KPK    4
#define NEGV   (-1.0e9f)
#define VTH    (-1.0e8f)
#define NPAIR  512            // B*N*C = 1*128*4
#define FULLM  0xffffffffu

// Compile-time axis coords: float((i-20)*0.3 computed in double) — bit-exact vs numpy
struct AxTable { float v[NXS]; };
static constexpr AxTable make_ax()
{
    AxTable t{};
    for (int i = 0; i < NXS; ++i) t.v[i] = (float)((double)(i - 20) * 0.3);
    return t;
}
__constant__ AxTable c_ax = make_ax();

// Shifted sphere masks: S_a bit p <-> voxel g = p + a. Tail words zero.
__device__ unsigned int g_S[4][WPAD];
__device__ int g_list[4][CHUNKS];   // non-empty chunk ids per variant
__device__ int g_nlist[4];

// ---------------------------------------------------------------------------
// Kernel 1: shifted sphere masks, pure fp32 (numpy-identical op sequence)
// ---------------------------------------------------------------------------
__global__ __launch_bounds__(256) void init_masks_kernel()
{
    int a = blockIdx.y;
    int p = blockIdx.x * 256 + threadIdx.x;   // shifted bit position
    int g = p + a;                            // absolute voxel index
    bool ok = false;
    if (g < GTOT) {
        int i = g / NX2;
        int j = (g / NXS) % NXS;
        int k = g % NXS;
        float x = c_ax.v[i];
        float y = c_ax.v[j];
        float z = c_ax.v[k];
        float s = __fadd_rn(__fadd_rn(__fmul_rn(x, x), __fmul_rn(y, y)), __fmul_rn(z, z));
        ok = (__fsqrt_rn(s) <= 6.0f);
    }
    unsigned int ballot = __ballot_sync(FULLM, ok);
    if ((threadIdx.x & 31) == 0) {
        int w = p >> 5;
        if (w < WPAD) g_S[a][w] = ballot;
    }
}

// ---------------------------------------------------------------------------
// Kernel 2: per-variant compact list of non-empty chunks (1 CTA, 4 warps)
// ---------------------------------------------------------------------------
__global__ __launch_bounds__(128) void build_lists_kernel()
{
    int a = threadIdx.x >> 5;
    int lane = threadIdx.x & 31;
    const unsigned int* S = g_S[a];
    int count = 0;
    for (int base = 0; base < CHUNKS; base += 32) {
        int c = base + lane;
        bool ne = false;
        if (c < CHUNKS)
            ne = (S[c * 4] | S[c * 4 + 1] | S[c * 4 + 2] | S[c * 4 + 3]) != 0u;
        unsigned int bal = __ballot_sync(FULLM, ne);
        int pos = count + __popc(bal & ((1u << lane) - 1u));
        if (ne) g_list[a][pos] = c;
        count += __popc(bal);
    }
    if (lane == 0) g_nlist[a] = count;
}

// order-preserving float->uint key; 0 = "masked" (below all real keys)
__device__ __forceinline__ unsigned int f2key(float v)
{
    int i = __float_as_int(v);
    return (unsigned int)(i ^ ((i >> 31) | 0x80000000));
}
__device__ __forceinline__ float key2f(unsigned int k)
{
    int i = (k & 0x80000000u) ? (int)(k ^ 0x80000000u) : (int)~k;
    return __int_as_float(i);
}
__device__ __forceinline__ unsigned int sext_bit(unsigned int w, int bitpos)
{
    return (unsigned int)(((int)(w << (31 - bitpos))) >> 31);
}

// ---------------------------------------------------------------------------
// Kernel 3 (fused): pipelined unmasked float4 chunk scan + verified argmax + NMS
// ---------------------------------------------------------------------------
__global__ __launch_bounds__(256) void peaks_kernel(
    const float* __restrict__ density,   // [512, G]
    const float* __restrict__ grid_xyz,  // [G, 3]
    const float* __restrict__ Rmats,     // [128, 3, 3]
    const float* __restrict__ tpos,      // [128, 3]
    const float* __restrict__ node_mask, // [128]
    float* __restrict__ out)             // 16384 floats
{
    __shared__ unsigned int smask[WPAD];    // live shifted bits
    __shared__ unsigned int ckey[CHUNKS];   // per-chunk max key (>= masked truth)
    __shared__ int          slist[CHUNKS];  // non-empty chunk ids
    __shared__ unsigned int swk[8];
    __shared__ int          sww[8];
    __shared__ float pk_score[KPK];
    __shared__ int   pk_idx[KPK];
    __shared__ int   pk_valid[KPK];
    __shared__ int   cur_i, cur_j, cur_k, cur_valid, s_done;
    __shared__ int   wlist[128];
    __shared__ int   wcount;

    const int pair = blockIdx.x;            // n*4 + c
    const int tid  = threadIdx.x;
    const int lane = tid & 31;
    const int wid  = tid >> 5;
    const int aoff = (-pair) & 3;           // alignment shift (voxels)
    const float4* __restrict__ dens4 =
        (const float4*)(density + (size_t)pair * GTOT + aoff);
    const unsigned int* __restrict__ S = g_S[aoff];
    const int* __restrict__ list = g_list[aoff];
    const int nl = g_nlist[aoff];

    for (int w = tid; w < WPAD; w += 256) smask[w] = S[w];
    for (int c = tid; c < CHUNKS; c += 256) { ckey[c] = 0u; slist[c] = list[c]; }
    __syncthreads();

    // ---- pass 1: UNMASKED per-chunk max over non-empty chunks, double-buffered ----
    {
        int    ccA[4];
        float4 ffA[4];
        int e0 = wid * 4;
        if (e0 < nl) {
            #pragma unroll
            for (int b = 0; b < 4; ++b) {
                int e = min(e0 + b, nl - 1);
                ccA[b] = slist[e];
                ffA[b] = __ldg(dens4 + ccA[b] * 32 + lane);
            }
        }
        for (; e0 < nl; e0 += 32) {
            int e1 = e0 + 32;
            int    ccB[4];
            float4 ffB[4];
            if (e1 < nl) {
                #pragma unroll
                for (int b = 0; b < 4; ++b) {
                    int e = min(e1 + b, nl - 1);
                    ccB[b] = slist[e];
                    ffB[b] = __ldg(dens4 + ccB[b] * 32 + lane);
                }
            }
            #pragma unroll
            for (int b = 0; b < 4; ++b) {
                float m = fmaxf(fmaxf(ffA[b].x, ffA[b].y), fmaxf(ffA[b].z, ffA[b].w));
                unsigned int r = __reduce_max_sync(FULLM, f2key(m));
                if (lane == 0 && e0 + b < nl) ckey[ccA[b]] = r;
            }
            if (e1 < nl) {
                #pragma unroll
                for (int b = 0; b < 4; ++b) { ccA[b] = ccB[b]; ffA[b] = ffB[b]; }
            }
        }
    }
    __syncthreads();

    for (int t = 0; t < KPK; ++t) {
        // ---- verified argmax loop ----
        for (;;) {
            unsigned int bk = 0;
            int bc = 0x7FFFFFFF;
            for (int c = tid; c < CHUNKS; c += 256) {
                unsigned int k = ckey[c];
                if (k > bk) { bk = k; bc = c; }   // ascending: lowest c on ties
            }
            unsigned int wm = __reduce_max_sync(FULLM, bk);
            int cand = (bk == wm) ? bc : 0x7FFFFFFF;
            int wmin = (int)__reduce_min_sync(FULLM, (unsigned int)cand);
            if (lane == 0) { swk[wid] = wm; sww[wid] = wmin; }
            __syncthreads();
            if (wid == 0) {
                unsigned int k8 = (lane < 8) ? swk[lane] : 0u;
                int w8 = (lane < 8) ? sww[lane] : 0x7FFFFFFF;
                unsigned int fm = __reduce_max_sync(FULLM, k8);
                int c8 = (k8 == fm) ? w8 : 0x7FFFFFFF;
                int fc = (int)__reduce_min_sync(FULLM, (unsigned int)c8);
                // masked verification of chunk fc
                float4 f = __ldg(dens4 + fc * 32 + lane);
                unsigned int mw = smask[fc * 4 + (lane >> 3)];
                int sh = (lane & 7) * 4;
                unsigned int k0 = f2key(f.x) & sext_bit(mw, sh + 0);
                unsigned int k1 = f2key(f.y) & sext_bit(mw, sh + 1);
                unsigned int k2 = f2key(f.z) & sext_bit(mw, sh + 2);
                unsigned int k3 = f2key(f.w) & sext_bit(mw, sh + 3);
                unsigned int bestk = k0; int besti = 0;
                if (k1 > bestk) { bestk = k1; besti = 1; }
                if (k2 > bestk) { bestk = k2; besti = 2; }
                if (k3 > bestk) { bestk = k3; besti = 3; }
                unsigned int mk = __reduce_max_sync(FULLM, bestk);
                if (mk == fm) {
                    // accept: lowest-g argmax within chunk
                    int gl = fc * 128 + lane * 4 + besti;
                    int cg = (bestk == mk) ? gl : 0x7FFFFFFF;
                    int gp = (int)__reduce_min_sync(FULLM, (unsigned int)cg);
                    if (lane == 0) {
                        int gi = gp + aoff;          // absolute voxel index
                        float sc = key2f(fm);
                        int valid = (sc > VTH) ? 1 : 0;
                        pk_score[t] = sc;
                        pk_idx[t]   = gi;
                        pk_valid[t] = valid;
                        cur_valid = valid;
                        cur_i = gi / NX2;
                        cur_j = (gi / NXS) % NXS;
                        cur_k = gi % NXS;
                        wcount = 0;
                        s_done = 1;
                    }
                } else {
                    if (lane == 0) { ckey[fc] = mk; s_done = 0; }
                }
            }
            __syncthreads();
            if (s_done) break;
        }

        if (t < KPK - 1 && cur_valid) {
            // ---- clear bits in <=7x7x7 Chebyshev cube (shifted coords) ----
            int i0 = max(cur_i - 3, 0), i1 = min(cur_i + 3, NXS - 1);
            int j0 = max(cur_j - 3, 0), j1 = min(cur_j + 3, NXS - 1);
            int k0c = max(cur_k - 3, 0), k1c = min(cur_k + 3, NXS - 1);
            int nj = j1 - j0 + 1;
            int nrows = (i1 - i0 + 1) * nj;
            // rows >=35 bits apart -> never share a 32-bit word -> no races
            if (tid < nrows) {
                int i = i0 + tid / nj;
                int j = j0 + tid % nj;
                int pb = i * NX2 + j * NXS + k0c - aoff;   // shifted position
                int pe = pb + (k1c - k0c);
                int w0 = pb >> 5, w1 = pe >> 5;
                unsigned int b0 = (unsigned int)(pb & 31);
                unsigned int b1 = (unsigned int)(pe & 31);
                unsigned int hi = (b1 == 31u) ? FULLM : ((1u << (b1 + 1)) - 1u);
                int slot;
                if (w0 == w1) {
                    unsigned int msk = hi & ~((1u << b0) - 1u);
                    smask[w0] &= ~msk;
                    slot = atomicAdd(&wcount, 1);
                    wlist[slot] = w0 >> 2;
                } else {
                    smask[w0] &= ((1u << b0) - 1u);
                    smask[w1] &= ~hi;
                    slot = atomicAdd(&wcount, 2);
                    wlist[slot]     = w0 >> 2;
                    wlist[slot + 1] = w1 >> 2;
                }
            }
            __syncthreads();
            // ---- masked recompute of touched chunks (exact) ----
            {
                int nw = wcount;   // <= 98, dups benign
                for (int e0 = wid * 4; e0 < nw; e0 += 32) {
                    int          cc[4];
                    float4       ff[4];
                    unsigned int mw_[4];
                    #pragma unroll
                    for (int b = 0; b < 4; ++b) {
                        int e = min(e0 + b, nw - 1);
                        int c = wlist[e];
                        cc[b] = (e0 + b < nw) ? c : -1;
                        ff[b] = __ldg(dens4 + c * 32 + lane);
                        mw_[b] = smask[c * 4 + (lane >> 3)];
                    }
                    int sh = (lane & 7) * 4;
                    #pragma unroll
                    for (int b = 0; b < 4; ++b) {
                        unsigned int mw = mw_[b];
                        unsigned int best = 0;
                        best = max(best, f2key(ff[b].x) & sext_bit(mw, sh + 0));
                        best = max(best, f2key(ff[b].y) & sext_bit(mw, sh + 1));
                        best = max(best, f2key(ff[b].z) & sext_bit(mw, sh + 2));
                        best = max(best, f2key(ff[b].w) & sext_bit(mw, sh + 3));
                        unsigned int r = __reduce_max_sync(FULLM, best);
                        if (lane == 0 && cc[b] >= 0) ckey[cc[b]] = r;
                    }
                }
            }
        }
        __syncthreads();
    }

    // ---- outputs ----
    // layout: coords_local[6144] | coords_global[6144] | scores[2048] | mask[2048]
    if (tid < KPK) {
        int k = tid;
        int n = pair >> 2;
        float nm = node_mask[n];
        int valid = pk_valid[k];
        float sc = valid ? pk_score[k] : NEGV;
        float x = 0.0f, y = 0.0f, z = 0.0f;
        if (valid) {
            int gi = pk_idx[k];
            x = grid_xyz[3 * gi + 0];
            y = grid_xyz[3 * gi + 1];
            z = grid_xyz[3 * gi + 2];
        }
        int o = (pair * KPK + k) * 3;
        out[o + 0] = x * nm;
        out[o + 1] = y * nm;
        out[o + 2] = z * nm;
        const float* R  = Rmats + n * 9;
        const float* tp = tpos + n * 3;
        float gx = R[0] * x + R[1] * y + R[2] * z + tp[0];
        float gy = R[3] * x + R[4] * y + R[5] * z + tp[1];
        float gz = R[6] * x + R[7] * y + R[8] * z + tp[2];
        out[6144 + o + 0] = gx * nm;
        out[6144 + o + 1] = gy * nm;
        out[6144 + o + 2] = gz * nm;
        out[12288 + pair * KPK + k] = sc * nm;
        out[14336 + pair * KPK + k] = (valid && nm != 0.0f) ? 1.0f : 0.0f;
    }
}

extern "C" void kernel_launch(void* const* d_in, const int* in_sizes, int n_in,
                              void* d_out, int out_size)
{
    // metadata order: density, grid_xyz, sphere_mask, coords_int, Rmats, tpos, node_mask
    const float* density   = (const float*)d_in[0];
    const float* grid_xyz  = (const float*)d_in[1];
    const float* Rmats     = (const float*)d_in[4];
    const float* tpos      = (const float*)d_in[5];
    const float* node_mask = (const float*)d_in[6];
    float* out = (float*)d_out;

    dim3 g1(270, 4);
    init_masks_kernel<<<g1, 256>>>();
    build_lists_kernel<<<1, 128>>>();
    peaks_kernel<<<NPAIR, 256>>>(density, grid_xyz, Rmats, tpos, node_mask, out);
}